// round 11
// baseline (speedup 1.0000x reference)
#include <cuda_runtime.h>
#include <cstdint>

// StructureTensorEffect, B=4, C=3, H=W=1024.
// Separable: s_u = Gx*Sy, s_v = Sx*Gy, per-batch-constant stencils.
// sigma in [0.5,2.5) => JP = floor(sigma) in {0,1,2}; templated on JP.
//
// R11 = R10 (f32x2 packed math) + R9 thread mapping:
//   512 threads/block, phase 2 = 1 row x 4 px per thread (6 packed accs),
//   phase 1 = 4-row chunks (408 active). __launch_bounds__(512,2) -> 64 regs,
//   2 blocks/SM = 32 warps.

#define Wd 1024
#define Hd 1024
#define TX 128
#define TY 16
#define HX 4
#define SW (TX + 2*HX)            // 136 floats per smem row
#define NTH 512
#define NSTRIP (SW/4)             // 34 float4 strips
#define CHUNK 4
#define NCHUNK (TY/CHUNK)         // 4
#define NVTASK (NSTRIP*NCHUNK*3)  // 408
#define HW (Hd*Wd)
#define SMEM_FLOATS (3*TY*SW)     // per array
#define SMEM_BYTES (2*SMEM_FLOATS*4)

// ---- f32x2 packed helpers (Blackwell FFMA2 path, PTX-only) ----
__device__ __forceinline__ uint64_t pk(float lo, float hi) {
    uint64_t r;
    asm("mov.b64 %0, {%1, %2};" : "=l"(r)
        : "r"(__float_as_uint(lo)), "r"(__float_as_uint(hi)));
    return r;
}
__device__ __forceinline__ void upk(uint64_t v, float& lo, float& hi) {
    uint32_t a, b;
    asm("mov.b64 {%0, %1}, %2;" : "=r"(a), "=r"(b) : "l"(v));
    lo = __uint_as_float(a); hi = __uint_as_float(b);
}
__device__ __forceinline__ uint64_t mul2(uint64_t a, uint64_t b) {
    uint64_t r; asm("mul.rn.f32x2 %0, %1, %2;" : "=l"(r) : "l"(a), "l"(b)); return r;
}
__device__ __forceinline__ uint64_t add2(uint64_t a, uint64_t b) {
    uint64_t r; asm("add.rn.f32x2 %0, %1, %2;" : "=l"(r) : "l"(a), "l"(b)); return r;
}
__device__ __forceinline__ uint64_t fma2(uint64_t a, uint64_t b, uint64_t c) {
    uint64_t r; asm("fma.rn.f32x2 %0, %1, %2, %3;" : "=l"(r) : "l"(a), "l"(b), "l"(c)); return r;
}
#define NEG1_2 0xBF800000BF800000ULL   // (-1.f, -1.f)
#define C100_2 0x42C8000042C80000ULL   // (100.f, 100.f)

__device__ __forceinline__ int clampi(int v, int lo, int hi) {
    return min(max(v, lo), hi);
}

// Exact per-pixel path replicating reference clip semantics (left/top only).
__device__ __noinline__ void exact_pixel(const float* __restrict__ xb, float s,
                                         int gx, int gy,
                                         float& A, float& Bv, float& Cv) {
    const float OU[8] = {-1.f,-1.f,-1.f, 0.f, 0.f, 1.f, 1.f, 1.f};
    const float OV[8] = {-1.f, 0.f, 1.f,-1.f, 1.f,-1.f, 0.f, 1.f};
    const float KU[8] = {-0.25f,-0.5f,-0.25f, 0.f, 0.f, 0.25f, 0.5f, 0.25f};
    const float KV[8] = {-0.25f, 0.f, 0.25f,-0.5f, 0.5f,-0.25f, 0.f, 0.25f};
    float su[3] = {0.f,0.f,0.f}, sv[3] = {0.f,0.f,0.f};
    #pragma unroll
    for (int t = 0; t < 8; ++t) {
        float px = (float)gx + OU[t] * s;
        float py = (float)gy + OV[t] * s;
        float x0f = floorf(px), y0f = floorf(py);
        float fx = px - x0f, fy = py - y0f;
        int x0 = clampi((int)x0f, 0, Wd - 1);
        int x1 = min(x0 + 1, Wd - 1);
        int y0 = clampi((int)y0f, 0, Hd - 1);
        int y1 = min(y0 + 1, Hd - 1);
        float w00 = (1.f - fx) * (1.f - fy);
        float w01 = fx * (1.f - fy);
        float w10 = (1.f - fx) * fy;
        float w11 = fx * fy;
        #pragma unroll
        for (int c = 0; c < 3; ++c) {
            const float* p = xb + c * HW;
            float bil = w00 * __ldg(&p[y0 * Wd + x0]) + w01 * __ldg(&p[y0 * Wd + x1])
                      + w10 * __ldg(&p[y1 * Wd + x0]) + w11 * __ldg(&p[y1 * Wd + x1]);
            su[c] += KU[t] * bil;
            sv[c] += KV[t] * bil;
        }
    }
    A = 0.f; Bv = 0.f; Cv = 0.f;
    #pragma unroll
    for (int c = 0; c < 3; ++c) {
        float l = (c == 0) ? 100.f : 1.f;
        float a = su[c] * l, b = sv[c] * l;
        A += a * a; Bv += b * b; Cv += a * b;
    }
}

struct P2 { uint64_t lo, hi; };   // packed float4

template<int JP>
__device__ __forceinline__ void run_tile(const float* __restrict__ xb, float s,
                                         float* __restrict__ smS,
                                         float* __restrict__ smG,
                                         float* __restrict__ out,
                                         int b, int bx0, int by0, int tid) {
    const float fp  = s - (float)JP;
    const float wp0 = 0.5f * (1.f - fp);
    const float wp1 = 0.5f * fp;
    const float wm0 = wp1;
    const float wm1 = wp0;

    // ---------------- Phase 1: vertical stencil (f32x2) -> smem ----------------
    if (tid < NVTASK) {
        const int c     = tid / (NSTRIP * NCHUNK);
        const int rem   = tid - c * (NSTRIP * NCHUNK);
        const int chunk = rem / NSTRIP;
        const int strip = rem - chunk * NSTRIP;

        const float* plane = xb + c * HW;
        const int gxu  = bx0 - HX + strip * 4;            // unclamped
        const bool edge = (gxu < 0) || (gxu > Wd - 4);
        const int cx0 = clampi(gxu + 0, 0, Wd - 1);
        const int cx1 = clampi(gxu + 1, 0, Wd - 1);
        const int cx2 = clampi(gxu + 2, 0, Wd - 1);
        const int cx3 = clampi(gxu + 3, 0, Wd - 1);
        const int ybase = by0 + chunk * CHUNK;

        const uint64_t Wm0 = pk(wm0, wm0), Wm1 = pk(wm1, wm1);
        const uint64_t Wp0 = pk(wp0, wp0), Wp1 = pk(wp1, wp1);

        auto ldrow = [&](int yy) -> P2 {
            const int yo = clampi(yy, 0, Hd - 1) * Wd;
            float4 v;
            if (!edge) {
                v = __ldg((const float4*)(plane + yo + gxu));
            } else {
                v.x = __ldg(plane + yo + cx0);
                v.y = __ldg(plane + yo + cx1);
                v.z = __ldg(plane + yo + cx2);
                v.w = __ldg(plane + yo + cx3);
            }
            P2 p; p.lo = pk(v.x, v.y); p.hi = pk(v.z, v.w);
            return p;
        };

        constexpr int WIN = 2 * JP + 3;
        P2 win[WIN];
        #pragma unroll
        for (int r = -JP - 1; r <= JP; ++r)
            win[r + JP + 1] = ldrow(ybase + r);

        float* sSrow = smS + (c * TY + chunk * CHUNK) * SW + strip * 4;
        float* sGrow = smG + (c * TY + chunk * CHUNK) * SW + strip * 4;

        #pragma unroll
        for (int j = 0; j < CHUNK; ++j) {
            win[(j + 2 * JP + 2) % WIN] = ldrow(ybase + j + JP + 1);

            P2 m0 = win[(j)              % WIN];
            P2 m1 = win[(j + 1)          % WIN];
            P2 ce = win[(j + JP + 1)     % WIN];
            P2 p0 = win[(j + 2 * JP + 1) % WIN];
            P2 p1 = win[(j + 2 * JP + 2) % WIN];

            uint64_t mpl = fma2(Wm1, m1.lo, mul2(Wm0, m0.lo));
            uint64_t mph = fma2(Wm1, m1.hi, mul2(Wm0, m0.hi));
            uint64_t ppl = fma2(Wp1, p1.lo, mul2(Wp0, p0.lo));
            uint64_t pph = fma2(Wp1, p1.hi, mul2(Wp0, p0.hi));
            uint64_t vsl = add2(ce.lo, add2(mpl, ppl));
            uint64_t vsh = add2(ce.hi, add2(mph, pph));
            uint64_t vgl = fma2(mpl, NEG1_2, ppl);       // pp - mp
            uint64_t vgh = fma2(mph, NEG1_2, pph);

            *(ulonglong2*)(sSrow + j * SW) = make_ulonglong2(vsl, vsh);
            *(ulonglong2*)(sGrow + j * SW) = make_ulonglong2(vgl, vgh);
        }
    }
    __syncthreads();

    // ---------------- Phase 2: horizontal stencil + packed quadratics ----------
    // 1 row x 4 px per thread: 32 col groups x 16 rows = 512 threads.
    const int cg = tid & 31;         // col group 0..31
    const int r  = tid >> 5;         // row 0..15
    const int xl = cg * 4;

    uint64_t qA[2] = {0, 0}, qB[2] = {0, 0}, qC[2] = {0, 0};

    constexpr int dM = 3 - JP;
    constexpr int dP = 4 + JP;

    #pragma unroll
    for (int c = 0; c < 3; ++c) {
        const float* Sp = smS + (c * TY + r) * SW + xl;
        const float* Gp = smG + (c * TY + r) * SW + xl;
        float4 a0 = *(const float4*)(Sp);
        float4 a1 = *(const float4*)(Sp + 4);
        float4 a2 = *(const float4*)(Sp + 8);
        float4 b0 = *(const float4*)(Gp);
        float4 b1 = *(const float4*)(Gp + 4);
        float4 b2 = *(const float4*)(Gp + 8);
        float sw[12] = {a0.x,a0.y,a0.z,a0.w, a1.x,a1.y,a1.z,a1.w, a2.x,a2.y,a2.z,a2.w};
        float gw[12] = {b0.x,b0.y,b0.z,b0.w, b1.x,b1.y,b1.z,b1.w, b2.x,b2.y,b2.z,b2.w};
        float su[4], sv[4];
        #pragma unroll
        for (int i = 0; i < 4; ++i) {
            su[i] = wp0 * sw[i + dP] + wp1 * sw[i + dP + 1]
                  - wm0 * sw[i + dM] - wm1 * sw[i + dM + 1];
            sv[i] = gw[i + 4]
                  + wm0 * gw[i + dM] + wm1 * gw[i + dM + 1]
                  + wp0 * gw[i + dP] + wp1 * gw[i + dP + 1];
        }
        uint64_t p01 = pk(su[0], su[1]), p23 = pk(su[2], su[3]);
        uint64_t q01 = pk(sv[0], sv[1]), q23 = pk(sv[2], sv[3]);
        if (c == 0) {                   // lum=100 channel; others lum=1
            p01 = mul2(p01, C100_2); p23 = mul2(p23, C100_2);
            q01 = mul2(q01, C100_2); q23 = mul2(q23, C100_2);
        }
        qA[0] = fma2(p01, p01, qA[0]);
        qA[1] = fma2(p23, p23, qA[1]);
        qB[0] = fma2(q01, q01, qB[0]);
        qB[1] = fma2(q23, q23, qB[1]);
        qC[0] = fma2(p01, q01, qC[0]);
        qC[1] = fma2(p23, q23, qC[1]);
    }

    // ---------------- Output ----------------
    float* out0 = out + (b * 3 + 0) * HW;
    float* out1 = out + (b * 3 + 1) * HW;
    float* out2 = out + (b * 3 + 2) * HW;
    const int gxg = bx0 + xl;
    const int gy  = by0 + r;
    const int o   = gy * Wd + gxg;

    float A[4], Bv[4], Cv[4];
    upk(qA[0], A[0], A[1]);   upk(qA[1], A[2], A[3]);
    upk(qB[0], Bv[0], Bv[1]); upk(qB[1], Bv[2], Bv[3]);
    upk(qC[0], Cv[0], Cv[1]); upk(qC[1], Cv[2], Cv[3]);

    // Right/bottom are exact via clamped taps; fallback only left/top.
    if (gxg >= 4 && gy > JP) {
        *(float4*)(out0 + o) = make_float4(A[0], A[1], A[2], A[3]);
        *(float4*)(out1 + o) = make_float4(Bv[0], Bv[1], Bv[2], Bv[3]);
        *(float4*)(out2 + o) = make_float4(Cv[0], Cv[1], Cv[2], Cv[3]);
    } else {
        #pragma unroll
        for (int i = 0; i < 4; ++i) {
            int gx = gxg + i;
            float a = A[i], bq = Bv[i], cq = Cv[i];
            if (gx <= JP || gy <= JP) {
                exact_pixel(xb, s, gx, gy, a, bq, cq);
            }
            out0[o + i] = a;
            out1[o + i] = bq;
            out2[o + i] = cq;
        }
    }
}

__global__ __launch_bounds__(NTH, 2)
void st11_kernel(const float* __restrict__ x, const float* __restrict__ sigma,
                 float* __restrict__ out) {
    extern __shared__ float sm[];
    float* smS = sm;
    float* smG = sm + SMEM_FLOATS;

    const int b   = blockIdx.z;
    const int bx0 = blockIdx.x * TX;
    const int by0 = blockIdx.y * TY;
    const int tid = threadIdx.x;

    const float s = __ldg(&sigma[b]);
    const int jp = clampi((int)floorf(s), 0, 2);
    const float* xb = x + b * 3 * HW;

    if (jp == 0)      run_tile<0>(xb, s, smS, smG, out, b, bx0, by0, tid);
    else if (jp == 1) run_tile<1>(xb, s, smS, smG, out, b, bx0, by0, tid);
    else              run_tile<2>(xb, s, smS, smG, out, b, bx0, by0, tid);
}

extern "C" void kernel_launch(void* const* d_in, const int* in_sizes, int n_in,
                              void* d_out, int out_size) {
    const float* x     = (const float*)d_in[0];
    const float* sigma = (const float*)d_in[1];
    float* out = (float*)d_out;
    int B = in_sizes[1];

    static_assert(SMEM_BYTES == 52224, "smem size");
    cudaFuncSetAttribute(st11_kernel, cudaFuncAttributeMaxDynamicSharedMemorySize, SMEM_BYTES);

    dim3 grid(Wd / TX, Hd / TY, B);                 // (8, 64, 4) = 2048 blocks
    st11_kernel<<<grid, NTH, SMEM_BYTES>>>(x, sigma, out);
}